// round 9
// baseline (speedup 1.0000x reference)
#include <cuda_runtime.h>
#include <cuda_bf16.h>
#include <cstdint>

#define NN   100000
#define EE   256000
#define EMB  300
#define EMB2 600
#define LAY  5
#define C75  (EMB / 4)
#define KP1  320   // padded K for GEMM1 (K=300)
#define KP2  608   // padded K for GEMM2 (K=600)

#define STAGE_BYTES 32768          // A hi/lo 16K + B hi/lo 16K (128x32 bf16 each)
#define NSTAGES 3
#define GEMM_SMEM (STAGE_BYTES * NSTAGES)

// ---------------- scratch ----------------
__device__ __align__(128) float g_agg [(size_t)NN * EMB];
__device__ __align__(128) float g_z1  [(size_t)NN * EMB2];
__device__ __align__(128) float g_z2  [(size_t)NN * EMB];
__device__ __align__(128) float g_h   [(size_t)NN * EMB];
__device__ __align__(128) float g_comb[18 * EMB];
__device__ __align__(128) float g_stats[1800];
__device__ __align__(128) float g_scale1[EMB2];
__device__ __align__(128) float g_shift1[EMB2];
__device__ __align__(128) float g_scale2[EMB];
__device__ __align__(128) float g_shift2[EMB];
// bf16 split planes (padded K)
__device__ __align__(128) __nv_bfloat16 g_aggH[(size_t)NN * KP1];
__device__ __align__(128) __nv_bfloat16 g_aggL[(size_t)NN * KP1];
__device__ __align__(128) __nv_bfloat16 g_z1aH[(size_t)NN * KP2];
__device__ __align__(128) __nv_bfloat16 g_z1aL[(size_t)NN * KP2];
__device__ __align__(128) __nv_bfloat16 g_w1H[EMB2 * KP1];
__device__ __align__(128) __nv_bfloat16 g_w1L[EMB2 * KP1];
__device__ __align__(128) __nv_bfloat16 g_w2H[EMB * KP2];
__device__ __align__(128) __nv_bfloat16 g_w2L[EMB * KP2];

// ---------------- helpers ----------------
__device__ __forceinline__ uint32_t smem_u32(const void* p) {
    uint32_t a;
    asm("{ .reg .u64 t; cvta.to.shared.u64 t, %1; cvt.u32.u64 %0, t; }" : "=r"(a) : "l"(p));
    return a;
}
__device__ __forceinline__ void ldsm4(uint32_t* r, uint32_t addr) {
    asm volatile("ldmatrix.sync.aligned.m8n8.x4.shared.b16 {%0,%1,%2,%3}, [%4];"
        : "=r"(r[0]), "=r"(r[1]), "=r"(r[2]), "=r"(r[3]) : "r"(addr));
}
__device__ __forceinline__ void mma16816(float* d, const uint32_t* a, uint32_t b0, uint32_t b1) {
    asm volatile("mma.sync.aligned.m16n8k16.row.col.f32.bf16.bf16.f32 "
        "{%0,%1,%2,%3}, {%4,%5,%6,%7}, {%8,%9}, {%0,%1,%2,%3};"
        : "+f"(d[0]), "+f"(d[1]), "+f"(d[2]), "+f"(d[3])
        : "r"(a[0]), "r"(a[1]), "r"(a[2]), "r"(a[3]), "r"(b0), "r"(b1));
}
__device__ __forceinline__ void split2(float x, float y, uint32_t& hi, uint32_t& lo) {
    __nv_bfloat16 hx = __float2bfloat16(x);
    __nv_bfloat16 hy = __float2bfloat16(y);
    float rx = x - __bfloat162float(hx);
    float ry = y - __bfloat162float(hy);
    __nv_bfloat16 lx = __float2bfloat16(rx);
    __nv_bfloat16 ly = __float2bfloat16(ry);
    hi = (uint32_t)__bfloat16_as_ushort(hx) | ((uint32_t)__bfloat16_as_ushort(hy) << 16);
    lo = (uint32_t)__bfloat16_as_ushort(lx) | ((uint32_t)__bfloat16_as_ushort(ly) << 16);
}
__device__ __forceinline__ uint32_t swz(int row, int kb) {
    return (uint32_t)(row * 64 + (((((kb >> 4) & 3) ^ ((row >> 1) & 3))) << 4) + (kb & 15));
}
__device__ __forceinline__ void cp16(uint32_t dst, const void* src, bool valid) {
    int sz = valid ? 16 : 0;
    asm volatile("cp.async.cg.shared.global [%0], [%1], 16, %2;"
        :: "r"(dst), "l"(src), "r"(sz) : "memory");
}
#define CP_COMMIT asm volatile("cp.async.commit_group;" ::: "memory")
#define CP_WAIT1  asm volatile("cp.async.wait_group 1;" ::: "memory")
#define CP_WAIT0  asm volatile("cp.async.wait_group 0;" ::: "memory")

// ---------------- small kernels ----------------
__global__ void build_comb(const float* __restrict__ Wb, int l) {
    int t = blockIdx.x * 256 + threadIdx.x;
    if (t < 18 * EMB) {
        int p = t / EMB;
        int f = t - p * EMB;
        int a = p / 3, b = p - a * 3;
        const float* w = Wb + (size_t)l * EMB * 9 + (size_t)f * 9;
        g_comb[p * EMB + f] = w[a] + w[6 + b];
    }
}
__global__ void zero_stats() {
    int t = blockIdx.x * 256 + threadIdx.x;
    if (t < 1800) g_stats[t] = 0.0f;
}
__global__ void init_agg(const float* __restrict__ x, int use_x, const float* __restrict__ eps, int l) {
    int i = blockIdx.x * 256 + threadIdx.x;
    if (i < NN * C75) {
        const float4* h = reinterpret_cast<const float4*>(use_x ? x : g_h);
        float s = 1.0f + eps[l];
        float4 v = h[i];
        v.x *= s; v.y *= s; v.z *= s; v.w *= s;
        reinterpret_cast<float4*>(g_agg)[i] = v;
    }
}
__global__ void edge_scatter(const float* __restrict__ x, int use_x,
                             const int* __restrict__ ei, const int* __restrict__ attr) {
    int idx = blockIdx.x * 256 + threadIdx.x;
    if (idx >= EE * C75) return;
    int e = idx / C75;
    int c = idx - e * C75;
    const float* h = use_x ? x : g_h;
    int src = ei[e];
    int dst = ei[EE + e];
    int2 av = *reinterpret_cast<const int2*>(attr + 2 * e);
    float4 hv = *reinterpret_cast<const float4*>(h + (size_t)src * EMB + 4 * c);
    float4 ev = *reinterpret_cast<const float4*>(g_comb + (av.x * 3 + av.y) * EMB + 4 * c);
    float4 m;
    m.x = fmaxf(hv.x + ev.x, 0.0f);
    m.y = fmaxf(hv.y + ev.y, 0.0f);
    m.z = fmaxf(hv.z + ev.z, 0.0f);
    m.w = fmaxf(hv.w + ev.w, 0.0f);
    float* a = g_agg + (size_t)dst * EMB + 4 * c;
    atomicAdd(a + 0, m.x);
    atomicAdd(a + 1, m.y);
    atomicAdd(a + 2, m.z);
    atomicAdd(a + 3, m.w);
}

// ---------------- split to bf16 hi/lo planes ----------------
// srcsel: 0 = external ptr (weights), 1 = g_agg, 2 = g_z1 (with bn1+relu transform)
// dstsel resolved in DEVICE code (host must never pass __device__ symbol addresses).
__global__ void split_fp32(const float* __restrict__ xsrc, int srcsel, int dstsel,
                           int rows, int K, int Kp) {
    const float* src = (srcsel == 1) ? g_agg : ((srcsel == 2) ? g_z1 : xsrc);
    __nv_bfloat16 *hi, *lo;
    switch (dstsel) {
        case 0:  hi = g_aggH; lo = g_aggL; break;
        case 1:  hi = g_z1aH; lo = g_z1aL; break;
        case 2:  hi = g_w1H;  lo = g_w1L;  break;
        default: hi = g_w2H;  lo = g_w2L;  break;
    }
    const int c8n = Kp >> 3;
    int idx = blockIdx.x * 256 + threadIdx.x;
    if (idx >= rows * c8n) return;
    int r = idx / c8n;
    int c8 = (idx - r * c8n) << 3;
    float v[8];
    const float* p = src + (size_t)r * K + c8;
    if (c8 + 8 <= K) {
        float4 a = *reinterpret_cast<const float4*>(p);
        float4 b = *reinterpret_cast<const float4*>(p + 4);
        v[0] = a.x; v[1] = a.y; v[2] = a.z; v[3] = a.w;
        v[4] = b.x; v[5] = b.y; v[6] = b.z; v[7] = b.w;
    } else {
#pragma unroll
        for (int j = 0; j < 8; j++) v[j] = (c8 + j < K) ? p[j] : 0.f;
    }
    if (srcsel == 2) {
#pragma unroll
        for (int j = 0; j < 8; j++)
            v[j] = (c8 + j < K) ? fmaxf(fmaf(v[j], g_scale1[c8 + j], g_shift1[c8 + j]), 0.f) : 0.f;
    }
    uint4 h4, l4;
    split2(v[0], v[1], h4.x, l4.x);
    split2(v[2], v[3], h4.y, l4.y);
    split2(v[4], v[5], h4.z, l4.z);
    split2(v[6], v[7], h4.w, l4.w);
    *reinterpret_cast<uint4*>(hi + (size_t)r * Kp + c8) = h4;
    *reinterpret_cast<uint4*>(lo + (size_t)r * Kp + c8) = l4;
}

// ---------------- bf16x3 GEMM, 3-stage cp.async, 128x128 block ----------------
// 512 threads = 16 warps (4M x 4N), warp tile 32x32, BK=32
// stage (32768B): AH[8192] AL[8192] BH[8192] BL[8192]
__global__ __launch_bounds__(512, 1)
void gemm_bf16(int sel, const float* __restrict__ bias, int M, int Nc, int nChunks) {
    extern __shared__ __align__(1024) char sm[];
    const uint32_t smBase = smem_u32(sm);

    const __nv_bfloat16 *Ah, *Al, *Bh, *Bl;
    int ldk;
    float *Cout, *statSum, *statSq;
    if (sel == 0) {
        Ah = g_aggH; Al = g_aggL; Bh = g_w1H; Bl = g_w1L; ldk = KP1;
        Cout = g_z1; statSum = g_stats; statSq = g_stats + 600;
    } else {
        Ah = g_z1aH; Al = g_z1aL; Bh = g_w2H; Bl = g_w2L; ldk = KP2;
        Cout = g_z2; statSum = g_stats + 1200; statSq = g_stats + 1500;
    }

    const int tid = threadIdx.x;
    const int wid = tid >> 5;
    const int lane = tid & 31;
    const int row0 = blockIdx.y * 128;
    const int col0 = blockIdx.x * 128;

    // cp.async mapping: 1 row (of A and of B) per thread, 16B each of hi/lo
    const int la_r = tid >> 2;    // 0..127
    const int la_c = tid & 3;     // 8-element chunk within 32

    float acc[2][4][4];
#pragma unroll
    for (int i = 0; i < 2; i++)
#pragma unroll
        for (int j = 0; j < 4; j++)
#pragma unroll
            for (int r = 0; r < 4; r++) acc[i][j][r] = 0.f;

    const int wm = wid & 3;       // M warp 0..3
    const int wn = wid >> 2;      // N warp 0..3
    const int wr = wm * 32;
    const int wc = wn * 32;

    // ---- stage loader: 4 cp.async x 16B per thread ----
    auto load_stage = [&](int slot, int ch) {
        const int k0 = ch * 32;
        const uint32_t base = smBase + slot * STAGE_BYTES;
        const uint32_t off = (uint32_t)(la_r * 64 + ((la_c ^ ((la_r >> 1) & 3)) << 4));
        {
            bool v = (row0 + la_r) < M;
            size_t gr = v ? (size_t)(row0 + la_r) : 0;
            cp16(base + off,        Ah + gr * ldk + k0 + la_c * 8, v);
            cp16(base + 8192 + off, Al + gr * ldk + k0 + la_c * 8, v);
        }
        {
            bool v = (col0 + la_r) < Nc;
            size_t gc = v ? (size_t)(col0 + la_r) : 0;
            cp16(base + 16384 + off, Bh + gc * ldk + k0 + la_c * 8, v);
            cp16(base + 24576 + off, Bl + gc * ldk + k0 + la_c * 8, v);
        }
    };

    // prologue: stages 0 and 1 (nChunks >= 2 always)
    load_stage(0, 0); CP_COMMIT;
    load_stage(1, 1); CP_COMMIT;

    for (int ch = 0; ch < nChunks; ch++) {
        if (ch + 1 < nChunks) { CP_WAIT1; } else { CP_WAIT0; }
        __syncthreads();
        if (ch + 2 < nChunks) {
            load_stage((ch + 2) % NSTAGES, ch + 2);
            CP_COMMIT;
        }

        const uint32_t base = smBase + (ch % NSTAGES) * STAGE_BYTES;
        const uint32_t aHi = base, aLo = base + 8192;
        const uint32_t bHi = base + 16384, bLo = base + 24576;
#pragma unroll
        for (int ks = 0; ks < 2; ks++) {
            const int kb = ks * 32 + ((lane >> 4) << 4);
            uint32_t ahi[2][4], alo[2][4];
#pragma unroll
            for (int i = 0; i < 2; i++) {
                uint32_t off = swz(wr + i * 16 + (lane & 15), kb);
                ldsm4(ahi[i], aHi + off);
                ldsm4(alo[i], aLo + off);
            }
#pragma unroll
            for (int jj = 0; jj < 2; jj++) {
                int rn = wc + jj * 16 + ((lane >> 3) & 1) * 8 + (lane & 7);
                uint32_t off = swz(rn, kb);
                uint32_t bh[4], bl[4];
                ldsm4(bh, bHi + off);
                ldsm4(bl, bLo + off);
#pragma unroll
                for (int i = 0; i < 2; i++) {
                    mma16816(acc[i][2 * jj],     ahi[i], bh[0], bh[2]);
                    mma16816(acc[i][2 * jj + 1], ahi[i], bh[1], bh[3]);
                    mma16816(acc[i][2 * jj],     ahi[i], bl[0], bl[2]);
                    mma16816(acc[i][2 * jj + 1], ahi[i], bl[1], bl[3]);
                    mma16816(acc[i][2 * jj],     alo[i], bh[0], bh[2]);
                    mma16816(acc[i][2 * jj + 1], alo[i], bh[1], bh[3]);
                }
            }
        }
    }
    __syncthreads();   // all compute done before smem reuse below

    // ---- epilogue: bias + store + BN stats ----
    float* sSum = reinterpret_cast<float*>(sm);
    float* sSq  = sSum + 128;
    if (tid < 128) { sSum[tid] = 0.f; sSq[tid] = 0.f; }
    __syncthreads();

    const int g  = lane >> 2;
    const int tg = lane & 3;
    float bv[8];
#pragma unroll
    for (int j = 0; j < 4; j++) {
        int gc = col0 + wc + j * 8 + tg * 2;
        bool cv = gc < Nc;
        bv[2 * j]     = cv ? bias[gc] : 0.f;
        bv[2 * j + 1] = cv ? bias[gc + 1] : 0.f;
    }
    float csum[8], csq[8];
#pragma unroll
    for (int k = 0; k < 8; k++) { csum[k] = 0.f; csq[k] = 0.f; }

#pragma unroll
    for (int i = 0; i < 2; i++) {
        int ra = row0 + wr + i * 16 + g;
        int rb = ra + 8;
#pragma unroll
        for (int j = 0; j < 4; j++) {
            int gc = col0 + wc + j * 8 + tg * 2;
            if (gc < Nc) {
                float o0 = acc[i][j][0] + bv[2 * j];
                float o1 = acc[i][j][1] + bv[2 * j + 1];
                if (ra < M) {
                    *reinterpret_cast<float2*>(Cout + (size_t)ra * Nc + gc) = make_float2(o0, o1);
                    csum[2 * j] += o0; csum[2 * j + 1] += o1;
                    csq[2 * j] += o0 * o0; csq[2 * j + 1] += o1 * o1;
                }
                float o2 = acc[i][j][2] + bv[2 * j];
                float o3 = acc[i][j][3] + bv[2 * j + 1];
                if (rb < M) {
                    *reinterpret_cast<float2*>(Cout + (size_t)rb * Nc + gc) = make_float2(o2, o3);
                    csum[2 * j] += o2; csum[2 * j + 1] += o3;
                    csq[2 * j] += o2 * o2; csq[2 * j + 1] += o3 * o3;
                }
            }
        }
    }
#pragma unroll
    for (int off = 4; off <= 16; off <<= 1) {
#pragma unroll
        for (int k = 0; k < 8; k++) {
            csum[k] += __shfl_xor_sync(0xffffffffu, csum[k], off);
            csq[k]  += __shfl_xor_sync(0xffffffffu, csq[k], off);
        }
    }
    if (lane < 4) {
#pragma unroll
        for (int j = 0; j < 4; j++) {
            int c = wc + j * 8 + lane * 2;
            if (col0 + c < Nc) {
                atomicAdd(&sSum[c], csum[2 * j]);
                atomicAdd(&sSum[c + 1], csum[2 * j + 1]);
                atomicAdd(&sSq[c], csq[2 * j]);
                atomicAdd(&sSq[c + 1], csq[2 * j + 1]);
            }
        }
    }
    __syncthreads();
    if (tid < 128 && col0 + tid < Nc) {
        atomicAdd(statSum + col0 + tid, sSum[tid]);
        atomicAdd(statSq + col0 + tid, sSq[tid]);
    }
}

__global__ void finalize_bn(const float* __restrict__ gamma, const float* __restrict__ beta,
                            int l, int sel) {
    int Ccols = sel ? EMB : EMB2;
    const float* sum = sel ? (g_stats + 1200) : g_stats;
    const float* sq  = sel ? (g_stats + 1500) : (g_stats + 600);
    float* scale = sel ? g_scale2 : g_scale1;
    float* shift = sel ? g_shift2 : g_shift1;
    int j = blockIdx.x * 256 + threadIdx.x;
    if (j < Ccols) {
        float inv = 1.0f / (float)NN;
        float m = sum[j] * inv;
        float v = sq[j] * inv - m * m;
        float sc = gamma[l * Ccols + j] * rsqrtf(v + 1e-5f);
        scale[j] = sc;
        shift[j] = beta[l * Ccols + j] - m * sc;
    }
}

__global__ void apply_out(float* __restrict__ dout, int use_dout, int do_relu) {
    int i = blockIdx.x * 256 + threadIdx.x;
    if (i < NN * C75) {
        int c4 = (i % C75) * 4;
        float4 v = reinterpret_cast<const float4*>(g_z2)[i];
        float4 sc = *reinterpret_cast<const float4*>(g_scale2 + c4);
        float4 sh = *reinterpret_cast<const float4*>(g_shift2 + c4);
        v.x = fmaf(v.x, sc.x, sh.x);
        v.y = fmaf(v.y, sc.y, sh.y);
        v.z = fmaf(v.z, sc.z, sh.z);
        v.w = fmaf(v.w, sc.w, sh.w);
        if (do_relu) {
            v.x = fmaxf(v.x, 0.f);
            v.y = fmaxf(v.y, 0.f);
            v.z = fmaxf(v.z, 0.f);
            v.w = fmaxf(v.w, 0.f);
        }
        float4* o = use_dout ? reinterpret_cast<float4*>(dout) : reinterpret_cast<float4*>(g_h);
        o[i] = v;
    }
}

// ---------------- host ----------------
extern "C" void kernel_launch(void* const* d_in, const int* in_sizes, int n_in,
                              void* d_out, int out_size) {
    const float* x    = (const float*)d_in[0];
    const float* Wb   = (const float*)d_in[1];
    const float* eps  = (const float*)d_in[2];
    const float* W1   = (const float*)d_in[3];
    const float* b1   = (const float*)d_in[4];
    const float* bn1g = (const float*)d_in[5];
    const float* bn1b = (const float*)d_in[6];
    const float* W2   = (const float*)d_in[7];
    const float* b2   = (const float*)d_in[8];
    const float* bng  = (const float*)d_in[9];
    const float* bnb  = (const float*)d_in[10];
    const int*   ei   = (const int*)d_in[11];
    const int*   attr = (const int*)d_in[12];
    float* out = (float*)d_out;

    cudaFuncSetAttribute(gemm_bf16, cudaFuncAttributeMaxDynamicSharedMemorySize, GEMM_SMEM);

    const int gridA = (NN * C75 + 255) / 256;
    const int gridE = (EE * C75 + 255) / 256;
    const int rowT  = (NN + 127) / 128;            // 782
    const int cb1   = (EMB2 + 127) / 128;          // 5
    const int cb2   = (EMB + 127) / 128;           // 3
    const int nch1  = KP1 / 32;                    // 10
    const int nch2  = KP2 / 32;                    // 19
    const int gsA   = (NN * (KP1 / 8) + 255) / 256;
    const int gsZ   = (NN * (KP2 / 8) + 255) / 256;
    const int gsW1  = (EMB2 * (KP1 / 8) + 255) / 256;
    const int gsW2  = (EMB * (KP2 / 8) + 255) / 256;

    for (int l = 0; l < LAY; l++) {
        int use_x = (l == 0) ? 1 : 0;
        build_comb<<<(18 * EMB + 255) / 256, 256>>>(Wb, l);
        zero_stats<<<(1800 + 255) / 256, 256>>>();
        init_agg<<<gridA, 256>>>(x, use_x, eps, l);
        edge_scatter<<<gridE, 256>>>(x, use_x, ei, attr);
        split_fp32<<<gsA, 256>>>(nullptr, 1, 0, NN, EMB, KP1);
        split_fp32<<<gsW1, 256>>>(W1 + (size_t)l * EMB2 * EMB, 0, 2, EMB2, EMB, KP1);
        gemm_bf16<<<dim3(cb1, rowT), 512, GEMM_SMEM>>>(0, b1 + l * EMB2, NN, EMB2, nch1);
        finalize_bn<<<(EMB2 + 255) / 256, 256>>>(bn1g, bn1b, l, 0);
        split_fp32<<<gsZ, 256>>>(nullptr, 2, 1, NN, EMB2, KP2);
        split_fp32<<<gsW2, 256>>>(W2 + (size_t)l * EMB * EMB2, 0, 3, EMB, EMB2, KP2);
        gemm_bf16<<<dim3(cb2, rowT), 512, GEMM_SMEM>>>(1, b2 + l * EMB, NN, EMB, nch2);
        finalize_bn<<<(EMB + 255) / 256, 256>>>(bng, bnb, l, 1);
        apply_out<<<gridA, 256>>>(out, (l == LAY - 1) ? 1 : 0, (l < LAY - 1) ? 1 : 0);
    }
}

// round 14
// speedup vs baseline: 1.2244x; 1.2244x over previous
#include <cuda_runtime.h>
#include <cuda_bf16.h>
#include <cstdint>

#define NN   100000
#define EE   256000
#define EMB  300
#define EMB2 600
#define LAY  5
#define C75  (EMB / 4)
#define KP1  320   // padded K for GEMM1 (K=300)
#define KP2  608   // padded K for GEMM2 (K=600)

#define STAGE_BYTES 24576
#define NSTAGES 3
#define GEMM_SMEM (STAGE_BYTES * NSTAGES)

// ---------------- scratch ----------------
__device__ __align__(128) float g_agg [(size_t)NN * EMB];
__device__ __align__(128) float g_z1  [(size_t)NN * EMB2];
__device__ __align__(128) float g_z2  [(size_t)NN * EMB];
__device__ __align__(128) float g_h   [(size_t)NN * EMB];
__device__ __align__(128) float g_comb[18 * EMB];
__device__ __align__(128) float g_stats[1800];
__device__ __align__(128) float g_scale1[EMB2];
__device__ __align__(128) float g_shift1[EMB2];
__device__ __align__(128) float g_scale2[EMB];
__device__ __align__(128) float g_shift2[EMB];
// bf16 split planes (padded K)
__device__ __align__(128) __nv_bfloat16 g_aggH[(size_t)NN * KP1];
__device__ __align__(128) __nv_bfloat16 g_aggL[(size_t)NN * KP1];
__device__ __align__(128) __nv_bfloat16 g_z1aH[(size_t)NN * KP2];
__device__ __align__(128) __nv_bfloat16 g_z1aL[(size_t)NN * KP2];
__device__ __align__(128) __nv_bfloat16 g_w1H[EMB2 * KP1];
__device__ __align__(128) __nv_bfloat16 g_w1L[EMB2 * KP1];
__device__ __align__(128) __nv_bfloat16 g_w2H[EMB * KP2];
__device__ __align__(128) __nv_bfloat16 g_w2L[EMB * KP2];

// ---------------- helpers ----------------
__device__ __forceinline__ uint32_t smem_u32(const void* p) {
    uint32_t a;
    asm("{ .reg .u64 t; cvta.to.shared.u64 t, %1; cvt.u32.u64 %0, t; }" : "=r"(a) : "l"(p));
    return a;
}
__device__ __forceinline__ void ldsm4(uint32_t* r, uint32_t addr) {
    asm volatile("ldmatrix.sync.aligned.m8n8.x4.shared.b16 {%0,%1,%2,%3}, [%4];"
        : "=r"(r[0]), "=r"(r[1]), "=r"(r[2]), "=r"(r[3]) : "r"(addr));
}
__device__ __forceinline__ void mma16816(float* d, const uint32_t* a, uint32_t b0, uint32_t b1) {
    asm volatile("mma.sync.aligned.m16n8k16.row.col.f32.bf16.bf16.f32 "
        "{%0,%1,%2,%3}, {%4,%5,%6,%7}, {%8,%9}, {%0,%1,%2,%3};"
        : "+f"(d[0]), "+f"(d[1]), "+f"(d[2]), "+f"(d[3])
        : "r"(a[0]), "r"(a[1]), "r"(a[2]), "r"(a[3]), "r"(b0), "r"(b1));
}
__device__ __forceinline__ void split2(float x, float y, uint32_t& hi, uint32_t& lo) {
    __nv_bfloat16 hx = __float2bfloat16(x);
    __nv_bfloat16 hy = __float2bfloat16(y);
    float rx = x - __bfloat162float(hx);
    float ry = y - __bfloat162float(hy);
    __nv_bfloat16 lx = __float2bfloat16(rx);
    __nv_bfloat16 ly = __float2bfloat16(ry);
    hi = (uint32_t)__bfloat16_as_ushort(hx) | ((uint32_t)__bfloat16_as_ushort(hy) << 16);
    lo = (uint32_t)__bfloat16_as_ushort(lx) | ((uint32_t)__bfloat16_as_ushort(ly) << 16);
}
__device__ __forceinline__ uint32_t swz(int row, int kb) {
    return (uint32_t)(row * 64 + (((((kb >> 4) & 3) ^ ((row >> 1) & 3))) << 4) + (kb & 15));
}
__device__ __forceinline__ void cp16(uint32_t dst, const void* src, bool valid) {
    int sz = valid ? 16 : 0;
    asm volatile("cp.async.cg.shared.global [%0], [%1], 16, %2;"
        :: "r"(dst), "l"(src), "r"(sz) : "memory");
}
#define CP_COMMIT asm volatile("cp.async.commit_group;" ::: "memory")
#define CP_WAIT1  asm volatile("cp.async.wait_group 1;" ::: "memory")
#define CP_WAIT0  asm volatile("cp.async.wait_group 0;" ::: "memory")
__device__ __forceinline__ void red_add_v4(float* ptr, float4 v) {
    asm volatile("red.global.add.v4.f32 [%0], {%1,%2,%3,%4};"
        :: "l"(ptr), "f"(v.x), "f"(v.y), "f"(v.z), "f"(v.w) : "memory");
}

// ---------------- small kernels ----------------
// merged: build comb table + zero stats
__global__ void layer_prep(const float* __restrict__ Wb, int l) {
    int t = blockIdx.x * 256 + threadIdx.x;
    if (t < 18 * EMB) {
        int p = t / EMB;
        int f = t - p * EMB;
        int a = p / 3, b = p - a * 3;
        const float* w = Wb + (size_t)l * EMB * 9 + (size_t)f * 9;
        g_comb[p * EMB + f] = w[a] + w[6 + b];
    }
    if (t < 1800) g_stats[t] = 0.0f;
}
// only used for layer 0 (later layers: fused into apply_out)
__global__ void init_agg(const float* __restrict__ x, const float* __restrict__ eps, int l) {
    int i = blockIdx.x * 256 + threadIdx.x;
    if (i < NN * C75) {
        float s = 1.0f + eps[l];
        float4 v = reinterpret_cast<const float4*>(x)[i];
        v.x *= s; v.y *= s; v.z *= s; v.w *= s;
        reinterpret_cast<float4*>(g_agg)[i] = v;
    }
}
__global__ void edge_scatter(const float* __restrict__ x, int use_x,
                             const int* __restrict__ ei, const int* __restrict__ attr) {
    int idx = blockIdx.x * 256 + threadIdx.x;
    if (idx >= EE * C75) return;
    int e = idx / C75;
    int c = idx - e * C75;
    const float* h = use_x ? x : g_h;
    int src = ei[e];
    int dst = ei[EE + e];
    int2 av = *reinterpret_cast<const int2*>(attr + 2 * e);
    float4 hv = *reinterpret_cast<const float4*>(h + (size_t)src * EMB + 4 * c);
    float4 ev = *reinterpret_cast<const float4*>(g_comb + (av.x * 3 + av.y) * EMB + 4 * c);
    float4 m;
    m.x = fmaxf(hv.x + ev.x, 0.0f);
    m.y = fmaxf(hv.y + ev.y, 0.0f);
    m.z = fmaxf(hv.z + ev.z, 0.0f);
    m.w = fmaxf(hv.w + ev.w, 0.0f);
    red_add_v4(g_agg + (size_t)dst * EMB + 4 * c, m);
}

// ---------------- split to bf16 hi/lo planes ----------------
// srcsel: 0 = external ptr (weights), 1 = g_agg, 2 = g_z1 (with bn1+relu transform)
// dstsel resolved in DEVICE code (host must never pass __device__ symbol addresses).
__global__ void split_fp32(const float* __restrict__ xsrc, int srcsel, int dstsel,
                           int rows, int K, int Kp) {
    const float* src = (srcsel == 1) ? g_agg : ((srcsel == 2) ? g_z1 : xsrc);
    __nv_bfloat16 *hi, *lo;
    switch (dstsel) {
        case 0:  hi = g_aggH; lo = g_aggL; break;
        case 1:  hi = g_z1aH; lo = g_z1aL; break;
        case 2:  hi = g_w1H;  lo = g_w1L;  break;
        default: hi = g_w2H;  lo = g_w2L;  break;
    }
    const int c8n = Kp >> 3;
    int idx = blockIdx.x * 256 + threadIdx.x;
    if (idx >= rows * c8n) return;
    int r = idx / c8n;
    int c8 = (idx - r * c8n) << 3;
    float v[8];
    const float* p = src + (size_t)r * K + c8;
    if (c8 + 8 <= K) {
        float4 a = *reinterpret_cast<const float4*>(p);
        float4 b = *reinterpret_cast<const float4*>(p + 4);
        v[0] = a.x; v[1] = a.y; v[2] = a.z; v[3] = a.w;
        v[4] = b.x; v[5] = b.y; v[6] = b.z; v[7] = b.w;
    } else {
#pragma unroll
        for (int j = 0; j < 8; j++) v[j] = (c8 + j < K) ? p[j] : 0.f;
    }
    if (srcsel == 2) {
#pragma unroll
        for (int j = 0; j < 8; j++)
            v[j] = (c8 + j < K) ? fmaxf(fmaf(v[j], g_scale1[c8 + j], g_shift1[c8 + j]), 0.f) : 0.f;
    }
    uint4 h4, l4;
    split2(v[0], v[1], h4.x, l4.x);
    split2(v[2], v[3], h4.y, l4.y);
    split2(v[4], v[5], h4.z, l4.z);
    split2(v[6], v[7], h4.w, l4.w);
    *reinterpret_cast<uint4*>(hi + (size_t)r * Kp + c8) = h4;
    *reinterpret_cast<uint4*>(lo + (size_t)r * Kp + c8) = l4;
}

// ---------------- bf16x3 GEMM, 3-stage cp.async pipeline (round-8 proven config) ----------------
// block 128x64, BK=32, 8 warps (4M x 2N), warp tile 32x32
// stage (24576B): AH[8192] AL[8192] BH[4096] BL[4096]; 3 stages in dynamic smem
__global__ __launch_bounds__(256, 2)
void gemm_bf16(int sel, const float* __restrict__ bias, int M, int Nc, int nChunks) {
    extern __shared__ __align__(1024) char sm[];
    const uint32_t smBase = smem_u32(sm);

    const __nv_bfloat16 *Ah, *Al, *Bh, *Bl;
    int ldk;
    float *Cout, *statSum, *statSq;
    if (sel == 0) {
        Ah = g_aggH; Al = g_aggL; Bh = g_w1H; Bl = g_w1L; ldk = KP1;
        Cout = g_z1; statSum = g_stats; statSq = g_stats + 600;
    } else {
        Ah = g_z1aH; Al = g_z1aL; Bh = g_w2H; Bl = g_w2L; ldk = KP2;
        Cout = g_z2; statSum = g_stats + 1200; statSq = g_stats + 1500;
    }

    const int tid = threadIdx.x;
    const int wid = tid >> 5;
    const int lane = tid & 31;
    const int row0 = blockIdx.y * 128;
    const int col0 = blockIdx.x * 64;

    const int la_r = tid >> 2;    // 0..63
    const int la_c = tid & 3;     // chunk-of-8 within 32

    float acc[2][4][4];
#pragma unroll
    for (int i = 0; i < 2; i++)
#pragma unroll
        for (int j = 0; j < 4; j++)
#pragma unroll
            for (int r = 0; r < 4; r++) acc[i][j][r] = 0.f;

    const int wm = wid >> 1;
    const int wn = wid & 1;
    const int wr = wm * 32;
    const int wc = wn * 32;

    auto load_stage = [&](int slot, int ch) {
        const int k0 = ch * 32;
        const uint32_t base = smBase + slot * STAGE_BYTES;
#pragma unroll
        for (int p = 0; p < 2; p++) {
            int r = la_r + p * 64;                 // A row 0..127
            uint32_t off = (uint32_t)(r * 64 + ((la_c ^ ((r >> 1) & 3)) << 4));
            bool v = (row0 + r) < M;
            size_t gr = v ? (size_t)(row0 + r) : 0;
            cp16(base + off,        Ah + gr * ldk + k0 + la_c * 8, v);
            cp16(base + 8192 + off, Al + gr * ldk + k0 + la_c * 8, v);
        }
        {
            int r = la_r;                          // B row 0..63
            uint32_t off = (uint32_t)(r * 64 + ((la_c ^ ((r >> 1) & 3)) << 4));
            bool v = (col0 + r) < Nc;
            size_t gc = v ? (size_t)(col0 + r) : 0;
            cp16(base + 16384 + off, Bh + gc * ldk + k0 + la_c * 8, v);
            cp16(base + 20480 + off, Bl + gc * ldk + k0 + la_c * 8, v);
        }
    };

    load_stage(0, 0); CP_COMMIT;
    load_stage(1, 1); CP_COMMIT;

    for (int ch = 0; ch < nChunks; ch++) {
        if (ch + 1 < nChunks) { CP_WAIT1; } else { CP_WAIT0; }
        __syncthreads();
        if (ch + 2 < nChunks) {
            load_stage((ch + 2) % NSTAGES, ch + 2);
            CP_COMMIT;
        }

        const uint32_t base = smBase + (ch % NSTAGES) * STAGE_BYTES;
        const uint32_t aHi = base, aLo = base + 8192;
        const uint32_t bHi = base + 16384, bLo = base + 20480;
#pragma unroll
        for (int ks = 0; ks < 2; ks++) {
            const int kb = ks * 32 + ((lane >> 4) << 4);
            uint32_t ahi[2][4], alo[2][4];
#pragma unroll
            for (int i = 0; i < 2; i++) {
                uint32_t off = swz(wr + i * 16 + (lane & 15), kb);
                ldsm4(ahi[i], aHi + off);
                ldsm4(alo[i], aLo + off);
            }
#pragma unroll
            for (int jj = 0; jj < 2; jj++) {
                int rn = wc + jj * 16 + ((lane >> 3) & 1) * 8 + (lane & 7);
                uint32_t off = swz(rn, kb);
                uint32_t bh[4], bl[4];
                ldsm4(bh, bHi + off);
                ldsm4(bl, bLo + off);
#pragma unroll
                for (int i = 0; i < 2; i++) {
                    mma16816(acc[i][2 * jj],     ahi[i], bh[0], bh[2]);
                    mma16816(acc[i][2 * jj + 1], ahi[i], bh[1], bh[3]);
                    mma16816(acc[i][2 * jj],     ahi[i], bl[0], bl[2]);
                    mma16816(acc[i][2 * jj + 1], ahi[i], bl[1], bl[3]);
                    mma16816(acc[i][2 * jj],     alo[i], bh[0], bh[2]);
                    mma16816(acc[i][2 * jj + 1], alo[i], bh[1], bh[3]);
                }
            }
        }
    }
    __syncthreads();   // all compute done before smem reuse below

    // ---- epilogue: bias + store + BN stats ----
    float* sSum = reinterpret_cast<float*>(sm);
    float* sSq  = sSum + 64;
    if (tid < 64) { sSum[tid] = 0.f; sSq[tid] = 0.f; }
    __syncthreads();

    const int g  = lane >> 2;
    const int tg = lane & 3;
    float bv[8];
#pragma unroll
    for (int j = 0; j < 4; j++) {
        int gc = col0 + wc + j * 8 + tg * 2;
        bool cv = gc < Nc;
        bv[2 * j]     = cv ? bias[gc] : 0.f;
        bv[2 * j + 1] = cv ? bias[gc + 1] : 0.f;
    }
    float csum[8], csq[8];
#pragma unroll
    for (int k = 0; k < 8; k++) { csum[k] = 0.f; csq[k] = 0.f; }

#pragma unroll
    for (int i = 0; i < 2; i++) {
        int ra = row0 + wr + i * 16 + g;
        int rb = ra + 8;
#pragma unroll
        for (int j = 0; j < 4; j++) {
            int gc = col0 + wc + j * 8 + tg * 2;
            if (gc < Nc) {
                float o0 = acc[i][j][0] + bv[2 * j];
                float o1 = acc[i][j][1] + bv[2 * j + 1];
                if (ra < M) {
                    *reinterpret_cast<float2*>(Cout + (size_t)ra * Nc + gc) = make_float2(o0, o1);
                    csum[2 * j] += o0; csum[2 * j + 1] += o1;
                    csq[2 * j] += o0 * o0; csq[2 * j + 1] += o1 * o1;
                }
                float o2 = acc[i][j][2] + bv[2 * j];
                float o3 = acc[i][j][3] + bv[2 * j + 1];
                if (rb < M) {
                    *reinterpret_cast<float2*>(Cout + (size_t)rb * Nc + gc) = make_float2(o2, o3);
                    csum[2 * j] += o2; csum[2 * j + 1] += o3;
                    csq[2 * j] += o2 * o2; csq[2 * j + 1] += o3 * o3;
                }
            }
        }
    }
#pragma unroll
    for (int off = 4; off <= 16; off <<= 1) {
#pragma unroll
        for (int k = 0; k < 8; k++) {
            csum[k] += __shfl_xor_sync(0xffffffffu, csum[k], off);
            csq[k]  += __shfl_xor_sync(0xffffffffu, csq[k], off);
        }
    }
    if (lane < 4) {
#pragma unroll
        for (int j = 0; j < 4; j++) {
            int c = wc + j * 8 + lane * 2;
            if (col0 + c < Nc) {
                atomicAdd(&sSum[c], csum[2 * j]);
                atomicAdd(&sSum[c + 1], csum[2 * j + 1]);
                atomicAdd(&sSq[c], csq[2 * j]);
                atomicAdd(&sSq[c + 1], csq[2 * j + 1]);
            }
        }
    }
    __syncthreads();
    if (tid < 64 && col0 + tid < Nc) {
        atomicAdd(statSum + col0 + tid, sSum[tid]);
        atomicAdd(statSq + col0 + tid, sSq[tid]);
    }
}

__global__ void finalize_bn(const float* __restrict__ gamma, const float* __restrict__ beta,
                            int l, int sel) {
    int Ccols = sel ? EMB : EMB2;
    const float* sum = sel ? (g_stats + 1200) : g_stats;
    const float* sq  = sel ? (g_stats + 1500) : (g_stats + 600);
    float* scale = sel ? g_scale2 : g_scale1;
    float* shift = sel ? g_shift2 : g_shift1;
    int j = blockIdx.x * 256 + threadIdx.x;
    if (j < Ccols) {
        float inv = 1.0f / (float)NN;
        float m = sum[j] * inv;
        float v = sq[j] * inv - m * m;
        float sc = gamma[l * Ccols + j] * rsqrtf(v + 1e-5f);
        scale[j] = sc;
        shift[j] = beta[l * Ccols + j] - m * sc;
    }
}

// BN2 apply; for inner layers also pre-computes g_agg = (1+eps[l+1]) * h (fused init_agg)
__global__ void apply_out(float* __restrict__ dout, int use_dout, int do_relu,
                          const float* __restrict__ eps, int lnext) {
    int i = blockIdx.x * 256 + threadIdx.x;
    if (i < NN * C75) {
        int c4 = (i % C75) * 4;
        float4 v = reinterpret_cast<const float4*>(g_z2)[i];
        float4 sc = *reinterpret_cast<const float4*>(g_scale2 + c4);
        float4 sh = *reinterpret_cast<const float4*>(g_shift2 + c4);
        v.x = fmaf(v.x, sc.x, sh.x);
        v.y = fmaf(v.y, sc.y, sh.y);
        v.z = fmaf(v.z, sc.z, sh.z);
        v.w = fmaf(v.w, sc.w, sh.w);
        if (do_relu) {
            v.x = fmaxf(v.x, 0.f);
            v.y = fmaxf(v.y, 0.f);
            v.z = fmaxf(v.z, 0.f);
            v.w = fmaxf(v.w, 0.f);
        }
        if (use_dout) {
            reinterpret_cast<float4*>(dout)[i] = v;
        } else {
            reinterpret_cast<float4*>(g_h)[i] = v;
            float s = 1.0f + eps[lnext];
            float4 a = make_float4(v.x * s, v.y * s, v.z * s, v.w * s);
            reinterpret_cast<float4*>(g_agg)[i] = a;
        }
    }
}

// ---------------- host ----------------
extern "C" void kernel_launch(void* const* d_in, const int* in_sizes, int n_in,
                              void* d_out, int out_size) {
    const float* x    = (const float*)d_in[0];
    const float* Wb   = (const float*)d_in[1];
    const float* eps  = (const float*)d_in[2];
    const float* W1   = (const float*)d_in[3];
    const float* b1   = (const float*)d_in[4];
    const float* bn1g = (const float*)d_in[5];
    const float* bn1b = (const float*)d_in[6];
    const float* W2   = (const float*)d_in[7];
    const float* b2   = (const float*)d_in[8];
    const float* bng  = (const float*)d_in[9];
    const float* bnb  = (const float*)d_in[10];
    const int*   ei   = (const int*)d_in[11];
    const int*   attr = (const int*)d_in[12];
    float* out = (float*)d_out;

    cudaFuncSetAttribute(gemm_bf16, cudaFuncAttributeMaxDynamicSharedMemorySize, GEMM_SMEM);

    const int gridA = (NN * C75 + 255) / 256;
    const int gridE = (EE * C75 + 255) / 256;
    const int rowT  = (NN + 127) / 128;            // 782
    const int cb1   = (EMB2 + 63) / 64;            // 10
    const int cb2   = (EMB + 63) / 64;             // 5
    const int nch1  = KP1 / 32;                    // 10
    const int nch2  = KP2 / 32;                    // 19
    const int gsA   = (NN * (KP1 / 8) + 255) / 256;
    const int gsZ   = (NN * (KP2 / 8) + 255) / 256;
    const int gsW1  = (EMB2 * (KP1 / 8) + 255) / 256;
    const int gsW2  = (EMB * (KP2 / 8) + 255) / 256;

    for (int l = 0; l < LAY; l++) {
        int use_x = (l == 0) ? 1 : 0;
        layer_prep<<<(18 * EMB + 255) / 256, 256>>>(Wb, l);
        if (l == 0) init_agg<<<gridA, 256>>>(x, eps, l);
        // for l > 0: g_agg pre-filled by previous layer's apply_out
        edge_scatter<<<gridE, 256>>>(x, use_x, ei, attr);
        split_fp32<<<gsA, 256>>>(nullptr, 1, 0, NN, EMB, KP1);
        split_fp32<<<gsW1, 256>>>(W1 + (size_t)l * EMB2 * EMB, 0, 2, EMB2, EMB, KP1);
        gemm_bf16<<<dim3(cb1, rowT), 256, GEMM_SMEM>>>(0, b1 + l * EMB2, NN, EMB2, nch1);
        finalize_bn<<<(EMB2 + 255) / 256, 256>>>(bn1g, bn1b, l, 0);
        split_fp32<<<gsZ, 256>>>(nullptr, 2, 1, NN, EMB2, KP2);
        split_fp32<<<gsW2, 256>>>(W2 + (size_t)l * EMB * EMB2, 0, 3, EMB, EMB2, KP2);
        gemm_bf16<<<dim3(cb2, rowT), 256, GEMM_SMEM>>>(1, b2 + l * EMB, NN, EMB, nch2);
        finalize_bn<<<(EMB + 255) / 256, 256>>>(bng, bnb, l, 1);
        apply_out<<<gridA, 256>>>(out, (l == LAY - 1) ? 1 : 0, (l < LAY - 1) ? 1 : 0,
                                  eps, (l + 1 < LAY) ? (l + 1) : 0);
    }
}

// round 16
// speedup vs baseline: 1.2438x; 1.0158x over previous
#include <cuda_runtime.h>
#include <cuda_bf16.h>
#include <cstdint>

#define NN   100000
#define EE   256000
#define EMB  300
#define EMB2 600
#define LAY  5
#define C75  (EMB / 4)
#define KP1  320   // padded K for GEMM1 (K=300)
#define KP2  608   // padded K for GEMM2 (K=600)

#define STAGE_BYTES 32768          // AH 8K | AL 8K | BH 8K | BL 8K  (128x32 bf16 tiles)
#define NSTAGES 3
#define GEMM_SMEM (STAGE_BYTES * NSTAGES)

// ---------------- scratch ----------------
__device__ __align__(128) float g_agg [(size_t)NN * EMB];
__device__ __align__(128) float g_z1  [(size_t)NN * EMB2];
__device__ __align__(128) float g_z2  [(size_t)NN * EMB];
__device__ __align__(128) float g_h   [(size_t)NN * EMB];
__device__ __align__(128) float g_comb[18 * EMB];
__device__ __align__(128) float g_stats[1800];
__device__ __align__(128) float g_scale1[EMB2];
__device__ __align__(128) float g_shift1[EMB2];
__device__ __align__(128) float g_scale2[EMB];
__device__ __align__(128) float g_shift2[EMB];
// bf16 split planes (padded K)
__device__ __align__(128) __nv_bfloat16 g_aggH[(size_t)NN * KP1];
__device__ __align__(128) __nv_bfloat16 g_aggL[(size_t)NN * KP1];
__device__ __align__(128) __nv_bfloat16 g_z1aH[(size_t)NN * KP2];
__device__ __align__(128) __nv_bfloat16 g_z1aL[(size_t)NN * KP2];
__device__ __align__(128) __nv_bfloat16 g_w1H[EMB2 * KP1];
__device__ __align__(128) __nv_bfloat16 g_w1L[EMB2 * KP1];
__device__ __align__(128) __nv_bfloat16 g_w2H[EMB * KP2];
__device__ __align__(128) __nv_bfloat16 g_w2L[EMB * KP2];

// ---------------- helpers ----------------
__device__ __forceinline__ uint32_t smem_u32(const void* p) {
    uint32_t a;
    asm("{ .reg .u64 t; cvta.to.shared.u64 t, %1; cvt.u32.u64 %0, t; }" : "=r"(a) : "l"(p));
    return a;
}
__device__ __forceinline__ void ldsm4(uint32_t* r, uint32_t addr) {
    asm volatile("ldmatrix.sync.aligned.m8n8.x4.shared.b16 {%0,%1,%2,%3}, [%4];"
        : "=r"(r[0]), "=r"(r[1]), "=r"(r[2]), "=r"(r[3]) : "r"(addr));
}
__device__ __forceinline__ void mma16816(float* d, const uint32_t* a, uint32_t b0, uint32_t b1) {
    asm volatile("mma.sync.aligned.m16n8k16.row.col.f32.bf16.bf16.f32 "
        "{%0,%1,%2,%3}, {%4,%5,%6,%7}, {%8,%9}, {%0,%1,%2,%3};"
        : "+f"(d[0]), "+f"(d[1]), "+f"(d[2]), "+f"(d[3])
        : "r"(a[0]), "r"(a[1]), "r"(a[2]), "r"(a[3]), "r"(b0), "r"(b1));
}
__device__ __forceinline__ void split2(float x, float y, uint32_t& hi, uint32_t& lo) {
    __nv_bfloat16 hx = __float2bfloat16(x);
    __nv_bfloat16 hy = __float2bfloat16(y);
    float rx = x - __bfloat162float(hx);
    float ry = y - __bfloat162float(hy);
    __nv_bfloat16 lx = __float2bfloat16(rx);
    __nv_bfloat16 ly = __float2bfloat16(ry);
    hi = (uint32_t)__bfloat16_as_ushort(hx) | ((uint32_t)__bfloat16_as_ushort(hy) << 16);
    lo = (uint32_t)__bfloat16_as_ushort(lx) | ((uint32_t)__bfloat16_as_ushort(ly) << 16);
}
__device__ __forceinline__ uint32_t swz(int row, int kb) {
    return (uint32_t)(row * 64 + (((((kb >> 4) & 3) ^ ((row >> 1) & 3))) << 4) + (kb & 15));
}
__device__ __forceinline__ void cp16(uint32_t dst, const void* src, bool valid) {
    int sz = valid ? 16 : 0;
    asm volatile("cp.async.cg.shared.global [%0], [%1], 16, %2;"
        :: "r"(dst), "l"(src), "r"(sz) : "memory");
}
#define CP_COMMIT asm volatile("cp.async.commit_group;" ::: "memory")
#define CP_WAIT1  asm volatile("cp.async.wait_group 1;" ::: "memory")
#define CP_WAIT0  asm volatile("cp.async.wait_group 0;" ::: "memory")
__device__ __forceinline__ void red_add_v4(float* ptr, float4 v) {
    asm volatile("red.global.add.v4.f32 [%0], {%1,%2,%3,%4};"
        :: "l"(ptr), "f"(v.x), "f"(v.y), "f"(v.z), "f"(v.w) : "memory");
}

// ---------------- small kernels ----------------
__global__ void layer_prep(const float* __restrict__ Wb, int l) {
    int t = blockIdx.x * 256 + threadIdx.x;
    if (t < 18 * EMB) {
        int p = t / EMB;
        int f = t - p * EMB;
        int a = p / 3, b = p - a * 3;
        const float* w = Wb + (size_t)l * EMB * 9 + (size_t)f * 9;
        g_comb[p * EMB + f] = w[a] + w[6 + b];
    }
    if (t < 1800) g_stats[t] = 0.0f;
}
__global__ void init_agg(const float* __restrict__ x, const float* __restrict__ eps, int l) {
    int i = blockIdx.x * 256 + threadIdx.x;
    if (i < NN * C75) {
        float s = 1.0f + eps[l];
        float4 v = reinterpret_cast<const float4*>(x)[i];
        v.x *= s; v.y *= s; v.z *= s; v.w *= s;
        reinterpret_cast<float4*>(g_agg)[i] = v;
    }
}
__global__ void edge_scatter(const float* __restrict__ x, int use_x,
                             const int* __restrict__ ei, const int* __restrict__ attr) {
    int idx = blockIdx.x * 256 + threadIdx.x;
    if (idx >= EE * C75) return;
    int e = idx / C75;
    int c = idx - e * C75;
    const float* h = use_x ? x : g_h;
    int src = ei[e];
    int dst = ei[EE + e];
    int2 av = *reinterpret_cast<const int2*>(attr + 2 * e);
    float4 hv = *reinterpret_cast<const float4*>(h + (size_t)src * EMB + 4 * c);
    float4 ev = *reinterpret_cast<const float4*>(g_comb + (av.x * 3 + av.y) * EMB + 4 * c);
    float4 m;
    m.x = fmaxf(hv.x + ev.x, 0.0f);
    m.y = fmaxf(hv.y + ev.y, 0.0f);
    m.z = fmaxf(hv.z + ev.z, 0.0f);
    m.w = fmaxf(hv.w + ev.w, 0.0f);
    red_add_v4(g_agg + (size_t)dst * EMB + 4 * c, m);
}

// ---------------- split to bf16 hi/lo planes ----------------
__global__ void split_fp32(const float* __restrict__ xsrc, int srcsel, int dstsel,
                           int rows, int K, int Kp) {
    const float* src = (srcsel == 1) ? g_agg : ((srcsel == 2) ? g_z1 : xsrc);
    __nv_bfloat16 *hi, *lo;
    switch (dstsel) {
        case 0:  hi = g_aggH; lo = g_aggL; break;
        case 1:  hi = g_z1aH; lo = g_z1aL; break;
        case 2:  hi = g_w1H;  lo = g_w1L;  break;
        default: hi = g_w2H;  lo = g_w2L;  break;
    }
    const int c8n = Kp >> 3;
    int idx = blockIdx.x * 256 + threadIdx.x;
    if (idx >= rows * c8n) return;
    int r = idx / c8n;
    int c8 = (idx - r * c8n) << 3;
    float v[8];
    const float* p = src + (size_t)r * K + c8;
    if (c8 + 8 <= K) {
        float4 a = *reinterpret_cast<const float4*>(p);
        float4 b = *reinterpret_cast<const float4*>(p + 4);
        v[0] = a.x; v[1] = a.y; v[2] = a.z; v[3] = a.w;
        v[4] = b.x; v[5] = b.y; v[6] = b.z; v[7] = b.w;
    } else {
#pragma unroll
        for (int j = 0; j < 8; j++) v[j] = (c8 + j < K) ? p[j] : 0.f;
    }
    if (srcsel == 2) {
#pragma unroll
        for (int j = 0; j < 8; j++)
            v[j] = (c8 + j < K) ? fmaxf(fmaf(v[j], g_scale1[c8 + j], g_shift1[c8 + j]), 0.f) : 0.f;
    }
    uint4 h4, l4;
    split2(v[0], v[1], h4.x, l4.x);
    split2(v[2], v[3], h4.y, l4.y);
    split2(v[4], v[5], h4.z, l4.z);
    split2(v[6], v[7], h4.w, l4.w);
    *reinterpret_cast<uint4*>(hi + (size_t)r * Kp + c8) = h4;
    *reinterpret_cast<uint4*>(lo + (size_t)r * Kp + c8) = l4;
}

// ---------------- bf16x3 GEMM, 3-stage cp.async, 128x128 block, 8 warps (4Mx2N) ----------------
// warp tile 32x64, BK=32, 256 threads, 2 CTAs/SM
__global__ __launch_bounds__(256, 2)
void gemm_bf16(int sel, const float* __restrict__ bias, int M, int Nc, int nChunks) {
    extern __shared__ __align__(1024) char sm[];
    const uint32_t smBase = smem_u32(sm);

    const __nv_bfloat16 *Ah, *Al, *Bh, *Bl;
    int ldk;
    float *Cout, *statSum, *statSq;
    if (sel == 0) {
        Ah = g_aggH; Al = g_aggL; Bh = g_w1H; Bl = g_w1L; ldk = KP1;
        Cout = g_z1; statSum = g_stats; statSq = g_stats + 600;
    } else {
        Ah = g_z1aH; Al = g_z1aL; Bh = g_w2H; Bl = g_w2L; ldk = KP2;
        Cout = g_z2; statSum = g_stats + 1200; statSq = g_stats + 1500;
    }

    const int tid = threadIdx.x;
    const int wid = tid >> 5;
    const int lane = tid & 31;
    const int row0 = blockIdx.y * 128;
    const int col0 = blockIdx.x * 128;

    const int la_r = tid >> 2;    // 0..63
    const int la_c = tid & 3;     // chunk-of-8 within 32

    float acc[2][8][4];
#pragma unroll
    for (int i = 0; i < 2; i++)
#pragma unroll
        for (int j = 0; j < 8; j++)
#pragma unroll
            for (int r = 0; r < 4; r++) acc[i][j][r] = 0.f;

    const int wm = wid >> 1;      // 0..3 (M)
    const int wn = wid & 1;       // 0..1 (N)
    const int wr = wm * 32;
    const int wc = wn * 64;

    // ---- stage loader: 8 cp.async x 16B per thread ----
    auto load_stage = [&](int slot, int ch) {
        const int k0 = ch * 32;
        const uint32_t base = smBase + slot * STAGE_BYTES;
#pragma unroll
        for (int p = 0; p < 2; p++) {
            int r = la_r + p * 64;                 // 0..127
            uint32_t off = (uint32_t)(r * 64 + ((la_c ^ ((r >> 1) & 3)) << 4));
            bool va = (row0 + r) < M;
            size_t gr = va ? (size_t)(row0 + r) : 0;
            cp16(base + off,        Ah + gr * ldk + k0 + la_c * 8, va);
            cp16(base + 8192 + off, Al + gr * ldk + k0 + la_c * 8, va);
            bool vb = (col0 + r) < Nc;
            size_t gc = vb ? (size_t)(col0 + r) : 0;
            cp16(base + 16384 + off, Bh + gc * ldk + k0 + la_c * 8, vb);
            cp16(base + 24576 + off, Bl + gc * ldk + k0 + la_c * 8, vb);
        }
    };

    load_stage(0, 0); CP_COMMIT;
    load_stage(1, 1); CP_COMMIT;

    for (int ch = 0; ch < nChunks; ch++) {
        if (ch + 1 < nChunks) { CP_WAIT1; } else { CP_WAIT0; }
        __syncthreads();
        if (ch + 2 < nChunks) {
            load_stage((ch + 2) % NSTAGES, ch + 2);
            CP_COMMIT;
        }

        const uint32_t base = smBase + (ch % NSTAGES) * STAGE_BYTES;
        const uint32_t aHi = base, aLo = base + 8192;
        const uint32_t bHi = base + 16384, bLo = base + 24576;
#pragma unroll
        for (int ks = 0; ks < 2; ks++) {
            const int kb = ks * 32 + ((lane >> 4) << 4);
            uint32_t ahi[2][4], alo[2][4];
#pragma unroll
            for (int i = 0; i < 2; i++) {
                uint32_t off = swz(wr + i * 16 + (lane & 15), kb);
                ldsm4(ahi[i], aHi + off);
                ldsm4(alo[i], aLo + off);
            }
#pragma unroll
            for (int jj = 0; jj < 4; jj++) {
                int rn = wc + jj * 16 + ((lane >> 3) & 1) * 8 + (lane & 7);
                uint32_t off = swz(rn, kb);
                uint32_t bh[4], bl[4];
                ldsm4(bh, bHi + off);
                ldsm4(bl, bLo + off);
#pragma unroll
                for (int i = 0; i < 2; i++) {
                    mma16816(acc[i][2 * jj],     ahi[i], bh[0], bh[2]);
                    mma16816(acc[i][2 * jj + 1], ahi[i], bh[1], bh[3]);
                    mma16816(acc[i][2 * jj],     ahi[i], bl[0], bl[2]);
                    mma16816(acc[i][2 * jj + 1], ahi[i], bl[1], bl[3]);
                    mma16816(acc[i][2 * jj],     alo[i], bh[0], bh[2]);
                    mma16816(acc[i][2 * jj + 1], alo[i], bh[1], bh[3]);
                }
            }
        }
    }
    __syncthreads();   // all compute done before smem reuse below

    // ---- epilogue: bias + store + BN stats ----
    float* sSum = reinterpret_cast<float*>(sm);
    float* sSq  = sSum + 128;
    if (tid < 128) { sSum[tid] = 0.f; sSq[tid] = 0.f; }
    __syncthreads();

    const int g  = lane >> 2;
    const int tg = lane & 3;
    float bv[16];
#pragma unroll
    for (int j = 0; j < 8; j++) {
        int gc = col0 + wc + j * 8 + tg * 2;
        bool cv = gc < Nc;
        bv[2 * j]     = cv ? bias[gc] : 0.f;
        bv[2 * j + 1] = cv ? bias[gc + 1] : 0.f;
    }
    float csum[16], csq[16];
#pragma unroll
    for (int k = 0; k < 16; k++) { csum[k] = 0.f; csq[k] = 0.f; }

#pragma unroll
    for (int i = 0; i < 2; i++) {
        int ra = row0 + wr + i * 16 + g;
        int rb = ra + 8;
#pragma unroll
        for (int j = 0; j < 8; j++) {
            int gc = col0 + wc + j * 8 + tg * 2;
            if (gc < Nc) {
                float o0 = acc[i][j][0] + bv[2 * j];
                float o1 = acc[i][j][1] + bv[2 * j + 1];
                if (ra < M) {
                    *reinterpret_cast<float2*>(Cout + (size_t)ra * Nc + gc) = make_float2(o0, o1);
                    csum[2 * j] += o0; csum[2 * j + 1] += o1;
                    csq[2 * j] += o0 * o0; csq[2 * j + 1] += o1 * o1;
                }
                float o2 = acc[i][j][2] + bv[2 * j];
                float o3 = acc[i][j][3] + bv[2 * j + 1];
                if (rb < M) {
                    *reinterpret_cast<float2*>(Cout + (size_t)rb * Nc + gc) = make_float2(o2, o3);
                    csum[2 * j] += o2; csum[2 * j + 1] += o3;
                    csq[2 * j] += o2 * o2; csq[2 * j + 1] += o3 * o3;
                }
            }
        }
    }
#pragma unroll
    for (int off = 4; off <= 16; off <<= 1) {
#pragma unroll
        for (int k = 0; k < 16; k++) {
            csum[k] += __shfl_xor_sync(0xffffffffu, csum[k], off);
            csq[k]  += __shfl_xor_sync(0xffffffffu, csq[k], off);
        }
    }
    if (lane < 4) {
#pragma unroll
        for (int j = 0; j < 8; j++) {
            int c = wc + j * 8 + lane * 2;
            if (col0 + c < Nc) {
                atomicAdd(&sSum[c], csum[2 * j]);
                atomicAdd(&sSum[c + 1], csum[2 * j + 1]);
                atomicAdd(&sSq[c], csq[2 * j]);
                atomicAdd(&sSq[c + 1], csq[2 * j + 1]);
            }
        }
    }
    __syncthreads();
    if (tid < 128 && col0 + tid < Nc) {
        atomicAdd(statSum + col0 + tid, sSum[tid]);
        atomicAdd(statSq + col0 + tid, sSq[tid]);
    }
}

__global__ void finalize_bn(const float* __restrict__ gamma, const float* __restrict__ beta,
                            int l, int sel) {
    int Ccols = sel ? EMB : EMB2;
    const float* sum = sel ? (g_stats + 1200) : g_stats;
    const float* sq  = sel ? (g_stats + 1500) : (g_stats + 600);
    float* scale = sel ? g_scale2 : g_scale1;
    float* shift = sel ? g_shift2 : g_shift1;
    int j = blockIdx.x * 256 + threadIdx.x;
    if (j < Ccols) {
        float inv = 1.0f / (float)NN;
        float m = sum[j] * inv;
        float v = sq[j] * inv - m * m;
        float sc = gamma[l * Ccols + j] * rsqrtf(v + 1e-5f);
        scale[j] = sc;
        shift[j] = beta[l * Ccols + j] - m * sc;
    }
}

// BN2 apply; for inner layers also pre-computes g_agg = (1+eps[l+1]) * h (fused init_agg)
__global__ void apply_out(float* __restrict__ dout, int use_dout, int do_relu,
                          const float* __restrict__ eps, int lnext) {
    int i = blockIdx.x * 256 + threadIdx.x;
    if (i < NN * C75) {
        int c4 = (i % C75) * 4;
        float4 v = reinterpret_cast<const float4*>(g_z2)[i];
        float4 sc = *reinterpret_cast<const float4*>(g_scale2 + c4);
        float4 sh = *reinterpret_cast<const float4*>(g_shift2 + c4);
        v.x = fmaf(v.x, sc.x, sh.x);
        v.y = fmaf(v.y, sc.y, sh.y);
        v.z = fmaf(v.z, sc.z, sh.z);
        v.w = fmaf(v.w, sc.w, sh.w);
        if (do_relu) {
            v.x = fmaxf(v.x, 0.f);
            v.y = fmaxf(v.y, 0.f);
            v.z = fmaxf(v.z, 0.f);
            v.w = fmaxf(v.w, 0.f);
        }
        if (use_dout) {
            reinterpret_cast<float4*>(dout)[i] = v;
        } else {
            reinterpret_cast<float4*>(g_h)[i] = v;
            float s = 1.0f + eps[lnext];
            float4 a = make_float4(v.x * s, v.y * s, v.z * s, v.w * s);
            reinterpret_cast<float4*>(g_agg)[i] = a;
        }
    }
}

// ---------------- host ----------------
extern "C" void kernel_launch(void* const* d_in, const int* in_sizes, int n_in,
                              void* d_out, int out_size) {
    const float* x    = (const float*)d_in[0];
    const float* Wb   = (const float*)d_in[1];
    const float* eps  = (const float*)d_in[2];
    const float* W1   = (const float*)d_in[3];
    const float* b1   = (const float*)d_in[4];
    const float* bn1g = (const float*)d_in[5];
    const float* bn1b = (const float*)d_in[6];
    const float* W2   = (const float*)d_in[7];
    const float* b2   = (const float*)d_in[8];
    const float* bng  = (const float*)d_in[9];
    const float* bnb  = (const float*)d_in[10];
    const int*   ei   = (const int*)d_in[11];
    const int*   attr = (const int*)d_in[12];
    float* out = (float*)d_out;

    cudaFuncSetAttribute(gemm_bf16, cudaFuncAttributeMaxDynamicSharedMemorySize, GEMM_SMEM);

    const int gridA = (NN * C75 + 255) / 256;
    const int gridE = (EE * C75 + 255) / 256;
    const int rowT  = (NN + 127) / 128;            // 782
    const int cb1   = (EMB2 + 127) / 128;          // 5
    const int cb2   = (EMB + 127) / 128;           // 3
    const int nch1  = KP1 / 32;                    // 10
    const int nch2  = KP2 / 32;                    // 19
    const int gsA   = (NN * (KP1 / 8) + 255) / 256;
    const int gsZ   = (NN * (KP2 / 8) + 255) / 256;
    const int gsW1  = (EMB2 * (KP1 / 8) + 255) / 256;
    const int gsW2  = (EMB * (KP2 / 8) + 255) / 256;

    for (int l = 0; l < LAY; l++) {
        int use_x = (l == 0) ? 1 : 0;
        layer_prep<<<(18 * EMB + 255) / 256, 256>>>(Wb, l);
        if (l == 0) init_agg<<<gridA, 256>>>(x, eps, l);
        edge_scatter<<<gridE, 256>>>(x, use_x, ei, attr);
        split_fp32<<<gsA, 256>>>(nullptr, 1, 0, NN, EMB, KP1);
        split_fp32<<<gsW1, 256>>>(W1 + (size_t)l * EMB2 * EMB, 0, 2, EMB2, EMB, KP1);
        gemm_bf16<<<dim3(cb1, rowT), 256, GEMM_SMEM>>>(0, b1 + l * EMB2, NN, EMB2, nch1);
        finalize_bn<<<(EMB2 + 255) / 256, 256>>>(bn1g, bn1b, l, 0);
        split_fp32<<<gsZ, 256>>>(nullptr, 2, 1, NN, EMB2, KP2);
        split_fp32<<<gsW2, 256>>>(W2 + (size_t)l * EMB * EMB2, 0, 3, EMB, EMB2, KP2);
        gemm_bf16<<<dim3(cb2, rowT), 256, GEMM_SMEM>>>(1, b2 + l * EMB, NN, EMB, nch2);
        finalize_bn<<<(EMB + 255) / 256, 256>>>(bng, bnb, l, 1);
        apply_out<<<gridA, 256>>>(out, (l == LAY - 1) ? 1 : 0, (l < LAY - 1) ? 1 : 0,
                                  eps, (l + 1 < LAY) ? (l + 1) : 0);
    }
}